// round 1
// baseline (speedup 1.0000x reference)
#include <cuda_runtime.h>
#include <cuda_bf16.h>
#include <math.h>

// Problem dims (fixed by the dataset)
#define BATCH 8
#define N1    2048
#define N2    2048
#define DIM   1024

// ---------------------------------------------------------------------------
// Device-global scratch (allocation-guard-safe): Q, K, V projections + scores.
// ---------------------------------------------------------------------------
__device__ float g_Q[(size_t)BATCH * N1 * DIM];     // 64 MB
__device__ float g_K[(size_t)BATCH * N2 * DIM];     // 64 MB
__device__ float g_V[(size_t)BATCH * N2 * DIM];     // 64 MB
__device__ float g_S[(size_t)BATCH * N1 * N2];      // 128 MB

// ---------------------------------------------------------------------------
// SGEMM: C[M,N] = A[M,K] * op(B) (+ bias), fp32, tiles 128x128x8, 256 threads,
// 8x8 per-thread accumulators.
//   TRANS_B = true : B is [N,K] row-major (both operands K-contiguous, "NT")
//   TRANS_B = false: B is [K,N] row-major ("NN")
// blockIdx.z indexes the batch via per-operand strides.
// All dims are multiples of the tile sizes for this problem -> no bounds checks.
// ---------------------------------------------------------------------------
#define BM 128
#define BN 128
#define BKT 8
#define TM 8
#define TN 8

template<bool TRANS_B, bool HAS_BIAS>
__global__ void __launch_bounds__(256, 2)
gemm_kernel(const float* __restrict__ A, const float* __restrict__ B,
            const float* __restrict__ bias, float* __restrict__ C,
            int M, int N, int K,
            size_t sA, size_t sB, size_t sC)
{
    A += (size_t)blockIdx.z * sA;
    B += (size_t)blockIdx.z * sB;
    C += (size_t)blockIdx.z * sC;

    __shared__ float As[BKT][BM + 4];
    __shared__ float Bs[BKT][BN + 4];

    const int tid = threadIdx.x;
    const int tx  = tid & 15;        // 0..15 -> column group
    const int ty  = tid >> 4;        // 0..15 -> row group

    const int rowBase = blockIdx.y * BM;
    const int colBase = blockIdx.x * BN;

    // A-tile (and NT B-tile) loader: 128 rows x 8 k, one float4 per thread
    const int ar = tid >> 1;          // 0..127
    const int ac = (tid & 1) * 4;     // 0 or 4
    // NN B-tile loader: 8 k-rows x 128 cols, one float4 per thread
    const int bk = tid >> 5;          // 0..7
    const int bc = (tid & 31) * 4;    // 0..124

    float acc[TM][TN];
#pragma unroll
    for (int i = 0; i < TM; i++)
#pragma unroll
        for (int j = 0; j < TN; j++) acc[i][j] = 0.f;

    for (int k0 = 0; k0 < K; k0 += BKT) {
        // ---- load A tile (transposed into smem: As[k][m]) ----
        float4 av = *(const float4*)(A + (size_t)(rowBase + ar) * K + k0 + ac);
        As[ac + 0][ar] = av.x;
        As[ac + 1][ar] = av.y;
        As[ac + 2][ar] = av.z;
        As[ac + 3][ar] = av.w;

        // ---- load B tile ----
        if (TRANS_B) {
            float4 bv = *(const float4*)(B + (size_t)(colBase + ar) * K + k0 + ac);
            Bs[ac + 0][ar] = bv.x;
            Bs[ac + 1][ar] = bv.y;
            Bs[ac + 2][ar] = bv.z;
            Bs[ac + 3][ar] = bv.w;
        } else {
            float4 bv = *(const float4*)(B + (size_t)(k0 + bk) * N + colBase + bc);
            *(float4*)&Bs[bk][bc] = bv;
        }
        __syncthreads();

#pragma unroll
        for (int kk = 0; kk < BKT; kk++) {
            float4 a0 = *(const float4*)&As[kk][ty * TM];
            float4 a1 = *(const float4*)&As[kk][ty * TM + 4];
            float4 b0 = *(const float4*)&Bs[kk][tx * TN];
            float4 b1 = *(const float4*)&Bs[kk][tx * TN + 4];
            float a[TM] = {a0.x, a0.y, a0.z, a0.w, a1.x, a1.y, a1.z, a1.w};
            float b[TN] = {b0.x, b0.y, b0.z, b0.w, b1.x, b1.y, b1.z, b1.w};
#pragma unroll
            for (int i = 0; i < TM; i++)
#pragma unroll
                for (int j = 0; j < TN; j++)
                    acc[i][j] = fmaf(a[i], b[j], acc[i][j]);
        }
        __syncthreads();
    }

    // ---- epilogue: optional bias add, vectorized store ----
#pragma unroll
    for (int i = 0; i < TM; i++) {
        const int row = rowBase + ty * TM + i;
        float* crow = C + (size_t)row * N + colBase + tx * TN;
#pragma unroll
        for (int j4 = 0; j4 < TN; j4 += 4) {
            float4 v;
            v.x = acc[i][j4 + 0];
            v.y = acc[i][j4 + 1];
            v.z = acc[i][j4 + 2];
            v.w = acc[i][j4 + 3];
            if (HAS_BIAS) {
                const float* bb = bias + colBase + tx * TN + j4;
                v.x += bb[0]; v.y += bb[1]; v.z += bb[2]; v.w += bb[3];
            }
            *(float4*)(crow + j4) = v;
        }
    }
}

// ---------------------------------------------------------------------------
// In-place row softmax over N2 columns. One block per row, 256 threads.
// Max-subtraction is mandatory: logits reach |s| ~ 100+ (no 1/sqrt(D) scale).
// ---------------------------------------------------------------------------
__global__ void __launch_bounds__(256)
softmax_kernel(float* __restrict__ S, int cols)
{
    float* row = S + (size_t)blockIdx.x * cols;
    const int tid = threadIdx.x;

    __shared__ float red[32];

    // 1) row max
    float m = -INFINITY;
    for (int i = tid * 4; i < cols; i += 256 * 4) {
        float4 v = *(const float4*)(row + i);
        m = fmaxf(m, fmaxf(fmaxf(v.x, v.y), fmaxf(v.z, v.w)));
    }
#pragma unroll
    for (int o = 16; o > 0; o >>= 1)
        m = fmaxf(m, __shfl_xor_sync(0xFFFFFFFFu, m, o));
    if ((tid & 31) == 0) red[tid >> 5] = m;
    __syncthreads();
    if (tid < 32) {
        float t = (tid < 8) ? red[tid] : -INFINITY;
#pragma unroll
        for (int o = 4; o > 0; o >>= 1)
            t = fmaxf(t, __shfl_xor_sync(0xFFFFFFFFu, t, o));
        if (tid == 0) red[0] = t;
    }
    __syncthreads();
    const float rowMax = red[0];
    __syncthreads();

    // 2) exp + sum
    float s = 0.f;
    for (int i = tid * 4; i < cols; i += 256 * 4) {
        float4 v = *(const float4*)(row + i);
        v.x = expf(v.x - rowMax);
        v.y = expf(v.y - rowMax);
        v.z = expf(v.z - rowMax);
        v.w = expf(v.w - rowMax);
        s += v.x + v.y + v.z + v.w;
        *(float4*)(row + i) = v;
    }
#pragma unroll
    for (int o = 16; o > 0; o >>= 1)
        s += __shfl_xor_sync(0xFFFFFFFFu, s, o);
    if ((tid & 31) == 0) red[tid >> 5] = s;
    __syncthreads();
    if (tid < 32) {
        float t = (tid < 8) ? red[tid] : 0.f;
#pragma unroll
        for (int o = 4; o > 0; o >>= 1)
            t += __shfl_xor_sync(0xFFFFFFFFu, t, o);
        if (tid == 0) red[0] = t;
    }
    __syncthreads();
    const float inv = 1.0f / red[0];

    // 3) normalize
    for (int i = tid * 4; i < cols; i += 256 * 4) {
        float4 v = *(const float4*)(row + i);
        v.x *= inv; v.y *= inv; v.z *= inv; v.w *= inv;
        *(float4*)(row + i) = v;
    }
}

// ---------------------------------------------------------------------------
// Launch: QKV projections -> scores -> softmax -> P*V (into d_out).
// Inputs per metadata order:
//   0 main_feature [B,N1,D]  1 feature [B,N2,D]
//   2 Wq [D,D]  3 bq [D]  4 Wk [D,D]  5 bk [D]  6 Wv [D,D]  7 bv [D]
// ---------------------------------------------------------------------------
extern "C" void kernel_launch(void* const* d_in, const int* in_sizes, int n_in,
                              void* d_out, int out_size)
{
    const float* mainf = (const float*)d_in[0];
    const float* feat  = (const float*)d_in[1];
    const float* Wq    = (const float*)d_in[2];
    const float* bq    = (const float*)d_in[3];
    const float* Wk    = (const float*)d_in[4];
    const float* bk    = (const float*)d_in[5];
    const float* Wv    = (const float*)d_in[6];
    const float* bv    = (const float*)d_in[7];
    float* out = (float*)d_out;

    float *Q, *K, *V, *S;
    cudaGetSymbolAddress((void**)&Q, g_Q);
    cudaGetSymbolAddress((void**)&K, g_K);
    cudaGetSymbolAddress((void**)&V, g_V);
    cudaGetSymbolAddress((void**)&S, g_S);

    // ---- QKV projections: [B*N, D] = X[B*N, D] @ W^T + b  (NT, with bias) ----
    {
        dim3 grid(DIM / BN, (BATCH * N1) / BM, 1);
        gemm_kernel<true, true><<<grid, 256>>>(mainf, Wq, bq, Q,
                                               BATCH * N1, DIM, DIM, 0, 0, 0);
        gemm_kernel<true, true><<<grid, 256>>>(feat, Wk, bk, K,
                                               BATCH * N2, DIM, DIM, 0, 0, 0);
        gemm_kernel<true, true><<<grid, 256>>>(feat, Wv, bv, V,
                                               BATCH * N2, DIM, DIM, 0, 0, 0);
    }

    // ---- scores: S[b] = Q[b] @ K[b]^T  (NT, batched) ----
    {
        dim3 grid(N2 / BN, N1 / BM, BATCH);
        gemm_kernel<true, false><<<grid, 256>>>(Q, K, nullptr, S,
                                                N1, N2, DIM,
                                                (size_t)N1 * DIM,
                                                (size_t)N2 * DIM,
                                                (size_t)N1 * N2);
    }

    // ---- softmax over last dim ----
    softmax_kernel<<<BATCH * N1, 256>>>(S, N2);

    // ---- out: O[b] = P[b] @ V[b]  (NN, batched) ----
    {
        dim3 grid(DIM / BN, N1 / BM, BATCH);
        gemm_kernel<false, false><<<grid, 256>>>(S, V, nullptr, out,
                                                 N1, DIM, N2,
                                                 (size_t)N1 * N2,
                                                 (size_t)N2 * DIM,
                                                 (size_t)N1 * DIM);
    }
}

// round 4
// speedup vs baseline: 2.1610x; 2.1610x over previous
#include <cuda_runtime.h>
#include <cuda_bf16.h>
#include <math.h>
#include <stdint.h>

// Problem dims (fixed)
#define BATCH 8
#define N1    2048
#define N2    2048
#define DIM   1024
#define KP_PROJ (3*DIM)   // 3072: split-encoded K for projections & scores
#define KP_PV   (3*N2)    // 6144: split-encoded K for P*V

// ---------------------------------------------------------------------------
// Scratch arena, 434 MB, tight lifetimes:
//   bufC [0,          +100663296) : Q'            ; then P' (first half)
//   bufA [100663296,  +100663296) : Xm' -> K'     ; then P' (second half)
//   bufS [201326592,  +134217728) : Xf' -> S (fp32)
//   bufV [335544320,  +100663296) : Vt'
//   bufW [436207616,  +18874368)  : Wq', Wk', Wv'
// P' (16384 x 6144 bf16 = 201326592 B) overlays bufC+bufA exactly.
// ---------------------------------------------------------------------------
#define OFF_C   ((size_t)0)
#define OFF_A   ((size_t)100663296)
#define OFF_S   ((size_t)201326592)
#define OFF_V   ((size_t)335544320)
#define OFF_W   ((size_t)436207616)
#define WSZ     ((size_t)6291456)
#define ARENA_BYTES ((size_t)455081984)

__device__ __align__(1024) unsigned char g_arena[ARENA_BYTES];

// ---------------------------------------------------------------------------
// PTX helpers (no lambdas anywhere)
// ---------------------------------------------------------------------------
__device__ __forceinline__ uint32_t smem_u32(const void* p) {
    return (uint32_t)__cvta_generic_to_shared(p);
}
__device__ __forceinline__ void cp_async16(uint32_t dst, const void* src) {
    asm volatile("cp.async.cg.shared.global [%0], [%1], 16;\n" :: "r"(dst), "l"(src));
}
__device__ __forceinline__ void cp_commit() {
    asm volatile("cp.async.commit_group;\n");
}
__device__ __forceinline__ void cp_wait_all() {
    asm volatile("cp.async.wait_group 0;\n");
}
__device__ __forceinline__ void ldsm4(uint32_t& r0, uint32_t& r1, uint32_t& r2, uint32_t& r3,
                                      uint32_t addr) {
    asm volatile("ldmatrix.sync.aligned.m8n8.x4.shared.b16 {%0,%1,%2,%3}, [%4];\n"
                 : "=r"(r0), "=r"(r1), "=r"(r2), "=r"(r3) : "r"(addr));
}
__device__ __forceinline__ void mma16816(float* d, const uint32_t* a, uint32_t b0, uint32_t b1) {
    asm volatile("mma.sync.aligned.m16n8k16.row.col.f32.bf16.bf16.f32 "
                 "{%0,%1,%2,%3}, {%4,%5,%6,%7}, {%8,%9}, {%0,%1,%2,%3};\n"
                 : "+f"(d[0]), "+f"(d[1]), "+f"(d[2]), "+f"(d[3])
                 : "r"(a[0]), "r"(a[1]), "r"(a[2]), "r"(a[3]), "r"(b0), "r"(b1));
}
__device__ __forceinline__ uint32_t pkbf(__nv_bfloat16 a, __nv_bfloat16 b) {
    return (uint32_t)__bfloat16_as_ushort(a) | ((uint32_t)__bfloat16_as_ushort(b) << 16);
}

// smem tile: logical [128 rows][32 k] bf16 in 64 physical 128B rows; 16B chunks
// XOR-swizzled -> conflict-free cp.async stores and ldmatrix reads.
__device__ __forceinline__ uint32_t sw_off(int r, int c) {
    int pr = r >> 1;
    int pc = ((r & 1) << 2) | c;
    return (uint32_t)(pr * 128 + ((pc ^ (pr & 7)) << 4));
}

#define BM 128
#define BN 128
#define BK 32

// global->smem tile load: A-tile + B-tile, 2 x 256 threads x 16B each
__device__ __forceinline__ void load_tile(const __nv_bfloat16* A, const __nv_bfloat16* B,
                                          int Kp, int mBase, int nBase, int tid,
                                          uint32_t da, uint32_t db, int k0)
{
#pragma unroll
    for (int p = 0; p < 2; p++) {
        int id = tid + p * 256;
        int r  = id >> 2;
        int c  = id & 3;
        uint32_t so = sw_off(r, c);
        cp_async16(da + so, A + (size_t)(mBase + r) * Kp + k0 + c * 8);
        cp_async16(db + so, B + (size_t)(nBase + r) * Kp + k0 + c * 8);
    }
    cp_commit();
}

// one BK=32 stage of MMAs from smem
__device__ __forceinline__ void compute_stage(uint32_t aB, uint32_t bB,
                                              int wm, int wn, int lane,
                                              float acc[4][4][4])
{
    const int lrow = lane & 15;
    const int lkc  = lane >> 4;
#pragma unroll
    for (int ks = 0; ks < 2; ks++) {
        uint32_t a[4][4], b[2][4];
#pragma unroll
        for (int mi = 0; mi < 4; mi++) {
            int r = wm * 64 + mi * 16 + lrow;
            ldsm4(a[mi][0], a[mi][1], a[mi][2], a[mi][3], aB + sw_off(r, ks * 2 + lkc));
        }
#pragma unroll
        for (int bi = 0; bi < 2; bi++) {
            int r = wn * 32 + bi * 16 + lrow;
            ldsm4(b[bi][0], b[bi][1], b[bi][2], b[bi][3], bB + sw_off(r, ks * 2 + lkc));
        }
#pragma unroll
        for (int mi = 0; mi < 4; mi++)
#pragma unroll
            for (int ni = 0; ni < 4; ni++)
                mma16816(acc[mi][ni], a[mi], b[ni >> 1][ni & 1], b[ni >> 1][2 + (ni & 1)]);
    }
}

// ---------------------------------------------------------------------------
// NT bf16 GEMM, fp32 accum. A[M,Kp], B[N,Kp] row-major (K-contiguous).
// 128x128x32 tiles, 256 threads (2x4 warps, 64x32 per warp), double-buffered.
// OM: 0 fp32 out; 1 split-A out [hi,hi,lo]; 2 split-B out [hi,lo,hi];
//     3 split-B out transposed per-batch (Vt).
// ---------------------------------------------------------------------------
template<int OM, bool HAS_BIAS>
__global__ void __launch_bounds__(256)
gemm_bf16(const __nv_bfloat16* __restrict__ A, const __nv_bfloat16* __restrict__ B,
          const float* __restrict__ bias, void* __restrict__ Cout,
          int Kp, size_t strA, size_t strB, size_t strC, int ldc)
{
    A += (size_t)blockIdx.z * strA;
    B += (size_t)blockIdx.z * strB;

    __shared__ __nv_bfloat16 sAb[2][BM * BK];
    __shared__ __nv_bfloat16 sBb[2][BN * BK];

    const int tid  = threadIdx.x;
    const int wid  = tid >> 5, lane = tid & 31;
    const int wm   = wid >> 2, wn = wid & 3;
    const int mBase = blockIdx.y * BM;
    const int nBase = blockIdx.x * BN;

    float acc[4][4][4];
#pragma unroll
    for (int i = 0; i < 4; i++)
#pragma unroll
        for (int j = 0; j < 4; j++)
#pragma unroll
            for (int r = 0; r < 4; r++) acc[i][j][r] = 0.f;

    const uint32_t sA[2] = { smem_u32(&sAb[0][0]), smem_u32(&sAb[1][0]) };
    const uint32_t sB[2] = { smem_u32(&sBb[0][0]), smem_u32(&sBb[1][0]) };

    const int KT = Kp / BK;
    load_tile(A, B, Kp, mBase, nBase, tid, sA[0], sB[0], 0);
    for (int kt = 0; kt < KT; kt++) {
        cp_wait_all();
        __syncthreads();
        if (kt + 1 < KT)
            load_tile(A, B, Kp, mBase, nBase, tid, sA[(kt + 1) & 1], sB[(kt + 1) & 1],
                      (kt + 1) * BK);
        compute_stage(sA[kt & 1], sB[kt & 1], wm, wn, lane, acc);
        __syncthreads();
    }

    // ---- epilogue ----
    const int grp = lane >> 2, qid = lane & 3;

    if (OM == 0) {
        float* C = (float*)Cout + (size_t)blockIdx.z * strC;
#pragma unroll
        for (int mi = 0; mi < 4; mi++)
#pragma unroll
            for (int ni = 0; ni < 4; ni++) {
                int m0 = mBase + wm * 64 + mi * 16 + grp;
                int n0 = nBase + wn * 32 + ni * 8 + qid * 2;
                *(float2*)(C + (size_t)m0 * ldc + n0) =
                    make_float2(acc[mi][ni][0], acc[mi][ni][1]);
                *(float2*)(C + (size_t)(m0 + 8) * ldc + n0) =
                    make_float2(acc[mi][ni][2], acc[mi][ni][3]);
            }
    } else if (OM == 1 || OM == 2) {
        __nv_bfloat16* C = (__nv_bfloat16*)Cout;
#pragma unroll
        for (int mi = 0; mi < 4; mi++)
#pragma unroll
            for (int ni = 0; ni < 4; ni++) {
                int m0 = mBase + wm * 64 + mi * 16 + grp;
                int n0 = nBase + wn * 32 + ni * 8 + qid * 2;
                float bv0 = HAS_BIAS ? bias[n0]     : 0.f;
                float bv1 = HAS_BIAS ? bias[n0 + 1] : 0.f;
#pragma unroll
                for (int rr = 0; rr < 2; rr++) {
                    int m = m0 + rr * 8;
                    float c0 = acc[mi][ni][rr * 2 + 0] + bv0;
                    float c1 = acc[mi][ni][rr * 2 + 1] + bv1;
                    __nv_bfloat16 h0 = __float2bfloat16(c0);
                    __nv_bfloat16 l0 = __float2bfloat16(c0 - __bfloat162float(h0));
                    __nv_bfloat16 h1 = __float2bfloat16(c1);
                    __nv_bfloat16 l1 = __float2bfloat16(c1 - __bfloat162float(h1));
                    uint32_t u0, u1, u2;
                    if (OM == 1) { u0 = pkbf(h0, h0); u1 = pkbf(l0, h1); u2 = pkbf(h1, l1); }
                    else         { u0 = pkbf(h0, l0); u1 = pkbf(h0, h1); u2 = pkbf(l1, h1); }
                    uint32_t* p = (uint32_t*)(C + (size_t)m * ldc + 3 * n0);
                    p[0] = u0; p[1] = u1; p[2] = u2;
                }
            }
    } else {  // OM == 3 : split-B transposed: C[m][n] -> Vt'[b][n][3*(m%N2)+slot]
        __nv_bfloat16* C = (__nv_bfloat16*)Cout;
#pragma unroll
        for (int mi = 0; mi < 4; mi++)
#pragma unroll
            for (int ni = 0; ni < 4; ni++) {
                int m0 = mBase + wm * 64 + mi * 16 + grp;
                int n0 = nBase + wn * 32 + ni * 8 + qid * 2;
#pragma unroll
                for (int rr = 0; rr < 2; rr++) {
                    int m  = m0 + rr * 8;
                    int b  = m >> 11;
                    int mm = m & 2047;
#pragma unroll
                    for (int cc = 0; cc < 2; cc++) {
                        int n   = n0 + cc;
                        float c = acc[mi][ni][rr * 2 + cc] + (HAS_BIAS ? bias[n] : 0.f);
                        __nv_bfloat16 h = __float2bfloat16(c);
                        __nv_bfloat16 l = __float2bfloat16(c - __bfloat162float(h));
                        __nv_bfloat16* p = C + (size_t)b * ((size_t)DIM * KP_PV)
                                             + (size_t)n * KP_PV + 3 * mm;
                        p[0] = h; p[1] = l; p[2] = h;
                    }
                }
            }
    }
}

// ---------------------------------------------------------------------------
// fp32 -> 3-slot bf16 split converters.  APAT: [hi,hi,lo]; else [hi,lo,hi].
// ---------------------------------------------------------------------------
template<bool APAT>
__global__ void __launch_bounds__(256)
split3_kernel(const float* __restrict__ x, __nv_bfloat16* __restrict__ y, int n4)
{
    int i = blockIdx.x * 256 + threadIdx.x;
    if (i >= n4) return;
    float4 v = ((const float4*)x)[i];
    float f[4] = {v.x, v.y, v.z, v.w};
    uint32_t w[6];
    __nv_bfloat16 h[4], l[4];
#pragma unroll
    for (int j = 0; j < 4; j++) {
        h[j] = __float2bfloat16(f[j]);
        l[j] = __float2bfloat16(f[j] - __bfloat162float(h[j]));
    }
    if (APAT) {
        w[0] = pkbf(h[0], h[0]); w[1] = pkbf(l[0], h[1]); w[2] = pkbf(h[1], l[1]);
        w[3] = pkbf(h[2], h[2]); w[4] = pkbf(l[2], h[3]); w[5] = pkbf(h[3], l[3]);
    } else {
        w[0] = pkbf(h[0], l[0]); w[1] = pkbf(h[0], h[1]); w[2] = pkbf(l[1], h[1]);
        w[3] = pkbf(h[2], l[2]); w[4] = pkbf(h[2], h[3]); w[5] = pkbf(l[3], h[3]);
    }
    uint2* o = (uint2*)(y + (size_t)12 * i);
    o[0] = make_uint2(w[0], w[1]);
    o[1] = make_uint2(w[2], w[3]);
    o[2] = make_uint2(w[4], w[5]);
}

// ---------------------------------------------------------------------------
// Softmax over 2048 fp32 logits/row -> split-A bf16 probs [hi,hi,lo].
// One block (256 threads) per row; row held in registers.
// ---------------------------------------------------------------------------
__global__ void __launch_bounds__(256)
softmax_split(const float* __restrict__ S, __nv_bfloat16* __restrict__ P)
{
    const float* src = S + (size_t)blockIdx.x * N2;
    __nv_bfloat16* dst = P + (size_t)blockIdx.x * KP_PV;
    const int tid = threadIdx.x;
    __shared__ float red[8];

    float4 v0 = ((const float4*)src)[tid];
    float4 v1 = ((const float4*)src)[tid + 256];

    float m = fmaxf(fmaxf(fmaxf(v0.x, v0.y), fmaxf(v0.z, v0.w)),
                    fmaxf(fmaxf(v1.x, v1.y), fmaxf(v1.z, v1.w)));
#pragma unroll
    for (int o = 16; o > 0; o >>= 1) m = fmaxf(m, __shfl_xor_sync(~0u, m, o));
    if ((tid & 31) == 0) red[tid >> 5] = m;
    __syncthreads();
    if (tid < 32) {
        float t = (tid < 8) ? red[tid] : -INFINITY;
#pragma unroll
        for (int o = 4; o > 0; o >>= 1) t = fmaxf(t, __shfl_xor_sync(~0u, t, o));
        if (tid == 0) red[0] = t;
    }
    __syncthreads();
    const float rowMax = red[0];
    __syncthreads();

    v0.x = expf(v0.x - rowMax); v0.y = expf(v0.y - rowMax);
    v0.z = expf(v0.z - rowMax); v0.w = expf(v0.w - rowMax);
    v1.x = expf(v1.x - rowMax); v1.y = expf(v1.y - rowMax);
    v1.z = expf(v1.z - rowMax); v1.w = expf(v1.w - rowMax);

    float s = v0.x + v0.y + v0.z + v0.w + v1.x + v1.y + v1.z + v1.w;
#pragma unroll
    for (int o = 16; o > 0; o >>= 1) s += __shfl_xor_sync(~0u, s, o);
    if ((tid & 31) == 0) red[tid >> 5] = s;
    __syncthreads();
    if (tid < 32) {
        float t = (tid < 8) ? red[tid] : 0.f;
#pragma unroll
        for (int o = 4; o > 0; o >>= 1) t += __shfl_xor_sync(~0u, t, o);
        if (tid == 0) red[0] = t;
    }
    __syncthreads();
    const float inv = 1.0f / red[0];

#pragma unroll
    for (int g = 0; g < 2; g++) {
        float4 v = g ? v1 : v0;
        int idx = g ? (tid + 256) : tid;
        float f[4] = {v.x * inv, v.y * inv, v.z * inv, v.w * inv};
        __nv_bfloat16 h[4], l[4];
#pragma unroll
        for (int j = 0; j < 4; j++) {
            h[j] = __float2bfloat16(f[j]);
            l[j] = __float2bfloat16(f[j] - __bfloat162float(h[j]));
        }
        uint32_t w[6];
        w[0] = pkbf(h[0], h[0]); w[1] = pkbf(l[0], h[1]); w[2] = pkbf(h[1], l[1]);
        w[3] = pkbf(h[2], h[2]); w[4] = pkbf(l[2], h[3]); w[5] = pkbf(h[3], l[3]);
        uint2* o = (uint2*)(dst + (size_t)12 * idx);
        o[0] = make_uint2(w[0], w[1]);
        o[1] = make_uint2(w[2], w[3]);
        o[2] = make_uint2(w[4], w[5]);
    }
}

// ---------------------------------------------------------------------------
// Launch.  Buffer lifetime plan (all read/write regions disjoint per step):
//  1. Xm' -> bufA, Xf' -> bufS, W' -> bufW
//  2. Q'  = gemm(bufA, Wq')      -> bufC
//  3. K'  = gemm(bufS, Wk')      -> bufA   (Xm' dead)
//  4. Vt' = gemm(bufS, Wv')      -> bufV   (Xf' dead after this)
//  5. S   = gemm(bufC, bufA)     -> bufS
//  6. P'  = softmax(bufS)        -> bufC+bufA span (Q',K' dead)
//  7. out = gemm(P', Vt')        -> d_out
// ---------------------------------------------------------------------------
extern "C" void kernel_launch(void* const* d_in, const int* in_sizes, int n_in,
                              void* d_out, int out_size)
{
    const float* mainf = (const float*)d_in[0];
    const float* feat  = (const float*)d_in[1];
    const float* Wq    = (const float*)d_in[2];
    const float* bq    = (const float*)d_in[3];
    const float* Wk    = (const float*)d_in[4];
    const float* bk    = (const float*)d_in[5];
    const float* Wv    = (const float*)d_in[6];
    const float* bv    = (const float*)d_in[7];
    float* out = (float*)d_out;

    unsigned char* arena;
    cudaGetSymbolAddress((void**)&arena, g_arena);

    __nv_bfloat16* bufC = (__nv_bfloat16*)(arena + OFF_C);   // Q', then P' half 1
    __nv_bfloat16* bufA = (__nv_bfloat16*)(arena + OFF_A);   // Xm', K', P' half 2
    __nv_bfloat16* XfS  = (__nv_bfloat16*)(arena + OFF_S);   // Xf' (then S)
    float*         S    = (float*)(arena + OFF_S);
    __nv_bfloat16* Vt3  = (__nv_bfloat16*)(arena + OFF_V);
    __nv_bfloat16* Wq3  = (__nv_bfloat16*)(arena + OFF_W);
    __nv_bfloat16* Wk3  = (__nv_bfloat16*)(arena + OFF_W + WSZ);
    __nv_bfloat16* Wv3  = (__nv_bfloat16*)(arena + OFF_W + 2 * WSZ);
    __nv_bfloat16* P3   = bufC;                              // spans bufC+bufA

    const int MX = BATCH * N1;   // 16384

    // 1) split-encode inputs and weights
    split3_kernel<true ><<<(MX * DIM / 4 + 255) / 256, 256>>>(mainf, bufA, MX * DIM / 4);
    split3_kernel<true ><<<(MX * DIM / 4 + 255) / 256, 256>>>(feat,  XfS,  MX * DIM / 4);
    split3_kernel<false><<<(DIM * DIM / 4 + 255) / 256, 256>>>(Wq, Wq3, DIM * DIM / 4);
    split3_kernel<false><<<(DIM * DIM / 4 + 255) / 256, 256>>>(Wk, Wk3, DIM * DIM / 4);
    split3_kernel<false><<<(DIM * DIM / 4 + 255) / 256, 256>>>(Wv, Wv3, DIM * DIM / 4);

    // 2-4) projections: M=16384, N=1024, Kp=3072
    {
        dim3 g(DIM / BN, MX / BM, 1);
        gemm_bf16<1, true><<<g, 256>>>(bufA, Wq3, bq, bufC, KP_PROJ, 0, 0, 0, 3 * DIM);
        gemm_bf16<2, true><<<g, 256>>>(XfS,  Wk3, bk, bufA, KP_PROJ, 0, 0, 0, 3 * DIM);
        gemm_bf16<3, true><<<g, 256>>>(XfS,  Wv3, bv, Vt3,  KP_PROJ, 0, 0, 0, 0);
    }

    // 5) scores: per-batch M=2048, N=2048, Kp=3072 -> S fp32
    {
        dim3 g(N2 / BN, N1 / BM, BATCH);
        gemm_bf16<0, false><<<g, 256>>>(bufC, bufA, nullptr, S, KP_PROJ,
                                        (size_t)N1 * KP_PROJ, (size_t)N2 * KP_PROJ,
                                        (size_t)N1 * N2, N2);
    }

    // 6) softmax -> P' (split-A bf16)
    softmax_split<<<BATCH * N1, 256>>>(S, P3);

    // 7) out = P @ V : per-batch M=2048, N=1024, Kp=6144
    {
        dim3 g(DIM / BN, N1 / BM, BATCH);
        gemm_bf16<0, false><<<g, 256>>>(P3, Vt3, nullptr, out, KP_PV,
                                        (size_t)N1 * KP_PV, (size_t)DIM * KP_PV,
                                        (size_t)N1 * DIM, DIM);
    }
}